// round 7
// baseline (speedup 1.0000x reference)
#include <cuda_runtime.h>
#include <cuda_fp16.h>
#include <cstdint>

// Problem dims
#define B   64
#define NN  2048
#define NC  32
#define IC  16
#define OC  32
#define KO  (NC * OC)      // 1024
#define NCHUNK 32          // blocks per batch for k_iter
#define NPB (NN / NCHUNK)  // 64 nodes per block
#define S   3              // cp.async pipeline stages

// ---------------- scratch (device globals; no runtime allocation) ----------
__device__ __half g_priors[(size_t)B * NN * KO];   // 268 MB fp16 priors [b][n][k][o]
__device__ float  g_logits[(size_t)B * NN * NC];   // 16 MB  logits  [b][n][k]
__device__ float  g_s[B * KO];                     // s accumulator (zeroed by squash)
__device__ float  g_out[B * KO];                   // current outputs v_i

// ---------------- cp.async helpers ----------------------------------------
__device__ __forceinline__ void cp_async16(uint32_t saddr, const void* gaddr) {
    asm volatile("cp.async.cg.shared.global [%0], [%1], 16;" :: "r"(saddr), "l"(gaddr));
}
__device__ __forceinline__ void cp_async4(uint32_t saddr, const void* gaddr) {
    asm volatile("cp.async.ca.shared.global [%0], [%1], 4;" :: "r"(saddr), "l"(gaddr));
}
#define CP_COMMIT()  asm volatile("cp.async.commit_group;" ::: "memory")
#define CP_WAIT(n)   asm volatile("cp.async.wait_group %0;" :: "n"(n) : "memory")

// ---------------- pass 0: priors = einsum('bni,nkio->bnko'), fp16 store ----
// One block per node n. W[n] (32x16x32 fp32 = 64KB) lives in registers,
// reused across all 64 batches. Packed f32x2 FMA doubles fp32 throughput.
__global__ void __launch_bounds__(256) k_priors(const float* __restrict__ x,
                                                const float* __restrict__ w) {
    const int n  = blockIdx.x;
    const int t  = threadIdx.x;
    const int k  = t >> 3;            // capsule 0..31
    const int og = (t & 7) * 4;       // out-channel group (4 consecutive o)

    // x packed as (v,v) f32x2 per element for broadcast FMA
    __shared__ unsigned long long sx[B][IC];   // 8 KB

    for (int idx = t; idx < B * IC; idx += 256) {
        int b = idx >> 4, i = idx & 15;
        float v = x[((size_t)b * NN + n) * IC + i];
        unsigned long long pv;
        asm("mov.b64 %0, {%1, %2};" : "=l"(pv) : "f"(v), "f"(v));
        sx[b][i] = pv;
    }

    // Load this thread's W slice: W[n][k][0..15][og..og+3] -> 32 packed pairs
    unsigned long long wp[2 * IC];
    const float* wbase = w + (((size_t)n * NC + k) * IC) * OC + og;
#pragma unroll
    for (int i = 0; i < IC; i++) {
        ulonglong2 v = *(const ulonglong2*)(wbase + (size_t)i * OC);
        wp[2 * i]     = v.x;   // (w[og],   w[og+1])
        wp[2 * i + 1] = v.y;   // (w[og+2], w[og+3])
    }
    __syncthreads();

    __half* pout = g_priors + (size_t)n * KO + (size_t)k * OC + og;
#pragma unroll 1
    for (int b = 0; b < B; b++) {
        unsigned long long a0 = 0ull, a1 = 0ull;
#pragma unroll
        for (int i = 0; i < IC; i++) {
            unsigned long long xv = sx[b][i];
            asm("fma.rn.f32x2 %0, %1, %2, %0;" : "+l"(a0) : "l"(xv), "l"(wp[2 * i]));
            asm("fma.rn.f32x2 %0, %1, %2, %0;" : "+l"(a1) : "l"(xv), "l"(wp[2 * i + 1]));
        }
        float f0, f1, f2, f3;
        asm("mov.b64 {%0, %1}, %2;" : "=f"(f0), "=f"(f1) : "l"(a0));
        asm("mov.b64 {%0, %1}, %2;" : "=f"(f2), "=f"(f3) : "l"(a1));
        __half2 h01 = __floats2half2_rn(f0, f1);
        __half2 h23 = __floats2half2_rn(f2, f3);
        uint2 st;
        st.x = *(const unsigned int*)&h01;
        st.y = *(const unsigned int*)&h23;
        *(uint2*)(pout + (size_t)b * NN * KO) = st;
    }
}

// ---------------- routing pass (fused delta + softmax + weighted sum) ------
// Grid: (NCHUNK, B). One warp processes one node at a time: lane = capsule k.
// 3-stage cp.async pipeline: 2 full nodes (2KB/warp each) permanently in
// flight per warp; the warp never exposes DRAM latency through the softmax
// dependency chain. Each lane only reads its own smem slot -> no barriers,
// wait_group alone orders the per-thread copies.
// ITER==0: uniform probs 1/NC. ITER==1: logits = delta0 (stored).
// ITER==2: logits = stored + delta1.
template <int ITER>
__global__ void __launch_bounds__(256, 2) k_iter() {
    extern __shared__ char pbuf[];         // S*8*32*64 = 49152 B priors stages
    const int b    = blockIdx.y;
    const int warp = threadIdx.x >> 5;
    const int lane = threadIdx.x & 31;     // capsule index k

    __shared__ float   s_s[NC * 33];       // padded: bank-conflict-free
    __shared__ __half2 s_outh[NC][17];     // out row as half2 pairs, padded
    __shared__ float   s_lg[S][8][32];     // logit pipeline (ITER==2)

    for (int idx = threadIdx.x; idx < NC * 33; idx += 256) s_s[idx] = 0.f;
    if (ITER > 0) {
        const float2* op = (const float2*)g_out + b * (KO / 2);
        for (int idx = threadIdx.x; idx < KO / 2; idx += 256) {
            int k = idx >> 4, r = idx & 15;
            s_outh[k][r] = __float22half2_rn(op[idx]);
        }
    }
    __syncthreads();

    float acc[OC];
#pragma unroll
    for (int j = 0; j < OC; j++) acc[j] = 0.f;

    const int n0 = blockIdx.x * NPB;
    const __half* base  = g_priors + ((size_t)b * NN + n0) * KO + (size_t)lane * OC;
    const float*  lbase = g_logits + ((size_t)b * NN + n0) * NC + lane;

    const uint32_t slot  = ((uint32_t)warp * 32 + lane) * 64;   // my 64B slot
    const uint32_t sbase = (uint32_t)__cvta_generic_to_shared(pbuf) + slot;
    const uint32_t STAGE_BYTES = 8 * 32 * 64;    // 16 KB per stage

    // prologue: launch stages 0..S-2
#pragma unroll
    for (int s = 0; s < S - 1; s++) {
        int pn = warp + 8 * s;
        if (pn < NPB) {
            const char* g = (const char*)(base + (size_t)pn * KO);
            uint32_t sa = sbase + (uint32_t)s * STAGE_BYTES;
            cp_async16(sa,      g);
            cp_async16(sa + 16, g + 16);
            cp_async16(sa + 32, g + 32);
            cp_async16(sa + 48, g + 48);
            if (ITER == 2)
                cp_async4((uint32_t)__cvta_generic_to_shared(&s_lg[s][warp][lane]),
                          lbase + pn * NC);
        }
        CP_COMMIT();
    }

    int stage = 0;
#pragma unroll 1
    for (int nn = warp; nn < NPB; nn += 8) {
        // ---- issue prefetch for node nn + 8*(S-1) into the freed stage ----
        int ps = stage + (S - 1); if (ps >= S) ps -= S;
        int pn = nn + 8 * (S - 1);
        if (pn < NPB) {
            const char* g = (const char*)(base + (size_t)pn * KO);
            uint32_t sa = sbase + (uint32_t)ps * STAGE_BYTES;
            cp_async16(sa,      g);
            cp_async16(sa + 16, g + 16);
            cp_async16(sa + 32, g + 32);
            cp_async16(sa + 48, g + 48);
            if (ITER == 2)
                cp_async4((uint32_t)__cvta_generic_to_shared(&s_lg[ps][warp][lane]),
                          lbase + pn * NC);
        }
        CP_COMMIT();
        CP_WAIT(S - 1);                    // current stage's group is complete

        // ---- read current node from my private smem slot ----
        uint4 u[4];
        {
            const uint4* sp = (const uint4*)(pbuf + slot
                                             + (uint32_t)stage * STAGE_BYTES);
#pragma unroll
            for (int q = 0; q < 4; q++) u[q] = sp[q];
        }

        const __half2* ph = (const __half2*)u;   // 16 half2 = 32 o-values
        float prob;
        if (ITER == 0) {
            prob = 1.0f / NC;
        } else {
            // delta = dot(p, out[k]) via 4 independent HFMA2 chains
            __half2 dh0 = __float2half2_rn(0.f), dh1 = dh0, dh2 = dh0, dh3 = dh0;
#pragma unroll
            for (int r = 0; r < 16; r += 4) {
                dh0 = __hfma2(ph[r + 0], s_outh[lane][r + 0], dh0);
                dh1 = __hfma2(ph[r + 1], s_outh[lane][r + 1], dh1);
                dh2 = __hfma2(ph[r + 2], s_outh[lane][r + 2], dh2);
                dh3 = __hfma2(ph[r + 3], s_outh[lane][r + 3], dh3);
            }
            float2 f0 = __half22float2(__hadd2(dh0, dh1));
            float2 f1 = __half22float2(__hadd2(dh2, dh3));
            float d = (f0.x + f0.y) + (f1.x + f1.y);

            float logit = d;
            if (ITER == 2) logit += s_lg[stage][warp][lane];
            if (ITER == 1)
                g_logits[((size_t)b * NN + n0 + nn) * NC + lane] = d;

            // softmax across the 32 lanes (= capsules)
            float mx = logit;
#pragma unroll
            for (int off = 16; off > 0; off >>= 1)
                mx = fmaxf(mx, __shfl_xor_sync(0xffffffffu, mx, off));
            float e = __expf(logit - mx);
            float se = e;
#pragma unroll
            for (int off = 16; off > 0; off >>= 1)
                se += __shfl_xor_sync(0xffffffffu, se, off);
            prob = e / se;
        }

#pragma unroll
        for (int r = 0; r < 16; r++) {
            float2 pf = __half22float2(ph[r]);
            acc[2 * r]     = fmaf(prob, pf.x, acc[2 * r]);
            acc[2 * r + 1] = fmaf(prob, pf.y, acc[2 * r + 1]);
        }

        stage++; if (stage == S) stage = 0;
    }

    // per-warp accumulators -> shared (conflict-free: 33-stride rows)
#pragma unroll
    for (int j = 0; j < OC; j++) atomicAdd(&s_s[lane * 33 + j], acc[j]);
    __syncthreads();

    for (int idx = threadIdx.x; idx < KO; idx += 256)
        atomicAdd(&g_s[b * KO + idx], s_s[(idx >> 5) * 33 + (idx & 31)]);
}

// ---------------- squash: v = (|s|^2/(1+|s|^2)) * s/|s| -------------------
// Grid: (NC, B), 32 threads (lane = o). Also re-zeros g_s so the next pass /
// next graph replay starts clean (keeps kernel_launch deterministic).
template <bool FINAL>
__global__ void k_squash(float* __restrict__ dst) {
    const int k = blockIdx.x, b = blockIdx.y, o = threadIdx.x;
    const int idx = b * KO + k * OC + o;
    float v = g_s[idx];
    g_s[idx] = 0.f;
    float sq = v * v;
#pragma unroll
    for (int off = 16; off > 0; off >>= 1)
        sq += __shfl_xor_sync(0xffffffffu, sq, off);
    float scale = sqrtf(sq) / (1.f + sq);   // = (sq/(1+sq)) / sqrt(sq)
    float out = v * scale;
    if (FINAL) dst[idx] = out;
    else       g_out[idx] = out;
}

// ---------------- launch ----------------------------------------------------
extern "C" void kernel_launch(void* const* d_in, const int* in_sizes, int n_in,
                              void* d_out, int out_size) {
    const float* x = (const float*)d_in[0];          // [B, NN, IC]
    const float* w = (const float*)d_in[1];          // [NN, NC, IC, OC]
    float* out = (float*)d_out;                      // [B, 1, NC, OC]

    const int DYN = S * 8 * 32 * 64;                 // 49152 B dynamic smem

    // Opt the k_iter instantiations into >48KB total smem (dyn + ~9.5KB
    // static). Host-side attribute set: not an allocation, not a sync, not a
    // stream op -> graph-capture-safe; idempotent on every call.
    cudaFuncSetAttribute(k_iter<0>, cudaFuncAttributeMaxDynamicSharedMemorySize, DYN);
    cudaFuncSetAttribute(k_iter<1>, cudaFuncAttributeMaxDynamicSharedMemorySize, DYN);
    cudaFuncSetAttribute(k_iter<2>, cudaFuncAttributeMaxDynamicSharedMemorySize, DYN);

    k_priors<<<NN, 256>>>(x, w);

    k_iter<0><<<dim3(NCHUNK, B), 256, DYN>>>();
    k_squash<false><<<dim3(NC, B), 32>>>(nullptr);

    k_iter<1><<<dim3(NCHUNK, B), 256, DYN>>>();
    k_squash<false><<<dim3(NC, B), 32>>>(nullptr);

    k_iter<2><<<dim3(NCHUNK, B), 256, DYN>>>();
    k_squash<true><<<dim3(NC, B), 32>>>(out);
}

// round 8
// speedup vs baseline: 1.0336x; 1.0336x over previous
#include <cuda_runtime.h>
#include <cuda_fp16.h>
#include <cstdint>

// Problem dims
#define B   64
#define NN  2048
#define NC  32
#define IC  16
#define OC  32
#define KO  (NC * OC)      // 1024
#define NCHUNK 32          // blocks per batch for k_iter
#define NPB (NN / NCHUNK)  // 64 nodes per block

// ---------------- scratch (device globals; no runtime allocation) ----------
__device__ __half g_priors[(size_t)B * NN * KO];   // 268 MB fp16 priors [b][n][k][o]
__device__ float  g_logits[(size_t)B * NN * NC];   // 16 MB  logits  [b][n][k]
__device__ float  g_s[B * KO];                     // s accumulator (zeroed by squash)
__device__ float  g_out[B * KO];                   // current outputs v_i

// ---------------- pass 0: priors = einsum('bni,nkio->bnko'), fp16 store ----
// One block per node n. W[n] (32x16x32 fp32 = 64KB) lives in registers,
// reused across all 64 batches. Packed f32x2 FMA doubles fp32 throughput.
__global__ void __launch_bounds__(256) k_priors(const float* __restrict__ x,
                                                const float* __restrict__ w) {
    const int n  = blockIdx.x;
    const int t  = threadIdx.x;
    const int k  = t >> 3;            // capsule 0..31
    const int og = (t & 7) * 4;       // out-channel group (4 consecutive o)

    // x packed as (v,v) f32x2 per element for broadcast FMA
    __shared__ unsigned long long sx[B][IC];   // 8 KB

    for (int idx = t; idx < B * IC; idx += 256) {
        int b = idx >> 4, i = idx & 15;
        float v = x[((size_t)b * NN + n) * IC + i];
        unsigned long long pv;
        asm("mov.b64 %0, {%1, %2};" : "=l"(pv) : "f"(v), "f"(v));
        sx[b][i] = pv;
    }

    // Load this thread's W slice: W[n][k][0..15][og..og+3] -> 32 packed pairs
    unsigned long long wp[2 * IC];
    const float* wbase = w + (((size_t)n * NC + k) * IC) * OC + og;
#pragma unroll
    for (int i = 0; i < IC; i++) {
        ulonglong2 v = *(const ulonglong2*)(wbase + (size_t)i * OC);
        wp[2 * i]     = v.x;   // (w[og],   w[og+1])
        wp[2 * i + 1] = v.y;   // (w[og+2], w[og+3])
    }
    __syncthreads();

    __half* pout = g_priors + (size_t)n * KO + (size_t)k * OC + og;
#pragma unroll 1
    for (int b = 0; b < B; b++) {
        unsigned long long a0 = 0ull, a1 = 0ull;
#pragma unroll
        for (int i = 0; i < IC; i++) {
            unsigned long long xv = sx[b][i];
            asm("fma.rn.f32x2 %0, %1, %2, %0;" : "+l"(a0) : "l"(xv), "l"(wp[2 * i]));
            asm("fma.rn.f32x2 %0, %1, %2, %0;" : "+l"(a1) : "l"(xv), "l"(wp[2 * i + 1]));
        }
        float f0, f1, f2, f3;
        asm("mov.b64 {%0, %1}, %2;" : "=f"(f0), "=f"(f1) : "l"(a0));
        asm("mov.b64 {%0, %1}, %2;" : "=f"(f2), "=f"(f3) : "l"(a1));
        __half2 h01 = __floats2half2_rn(f0, f1);
        __half2 h23 = __floats2half2_rn(f2, f3);
        uint2 st;
        st.x = *(const unsigned int*)&h01;
        st.y = *(const unsigned int*)&h23;
        *(uint2*)(pout + (size_t)b * NN * KO) = st;
    }
}

// ---------------- routing pass (fused delta + softmax + weighted sum) ------
// Grid: (NCHUNK, B). One warp processes one node at a time: lane = capsule k.
// Latency handling: prefetch.global.L2 pulls the node-row 3 iterations ahead
// (DRAM->L2, no registers, 1 warp-instr); a depth-1 register LDG prefetch then
// hits L2 and is hidden under the ~450-cycle softmax/accumulate chain.
// ITER==0 walks nodes in REVERSE so the tail of k_priors' write stream (still
// L2-resident) is consumed first.
// ITER==0: uniform probs 1/NC. ITER==1: logits = delta0 (stored).
// ITER==2: logits = stored + delta1.
template <int ITER>
__global__ void __launch_bounds__(256, 2) k_iter() {
    const int b    = blockIdx.y;
    const int warp = threadIdx.x >> 5;
    const int lane = threadIdx.x & 31;     // capsule index k

    __shared__ float   s_s[NC * 33];       // padded: bank-conflict-free
    __shared__ __half2 s_outh[NC][17];     // out row as half2 pairs, padded

    for (int idx = threadIdx.x; idx < NC * 33; idx += 256) s_s[idx] = 0.f;
    if (ITER > 0) {
        const float2* op = (const float2*)g_out + b * (KO / 2);
        for (int idx = threadIdx.x; idx < KO / 2; idx += 256) {
            int k = idx >> 4, r = idx & 15;
            s_outh[k][r] = __float22half2_rn(op[idx]);
        }
    }
    __syncthreads();

    float acc[OC];
#pragma unroll
    for (int j = 0; j < OC; j++) acc[j] = 0.f;

    const int n0 = blockIdx.x * NPB;
    const __half* nbase = g_priors + ((size_t)b * NN + n0) * KO;   // node rows
    const __half* base  = nbase + (size_t)lane * OC;               // + lane slot
    const float*  lbase = g_logits + ((size_t)b * NN + n0) * NC + lane;

    // address-only node remap: ITER 0 consumes nodes in reverse order
#define IDX(v) ((ITER == 0) ? (NPB - 1 - (v)) : (v))

    // prologue: register-load first node; L2-prefetch the next two rounds
    uint4 u[4];
    {
        const uint4* rp = (const uint4*)(base + (size_t)IDX(warp) * KO);
#pragma unroll
        for (int q = 0; q < 4; q++) u[q] = rp[q];
    }
    float lg = 0.f;
    if (ITER == 2) lg = lbase[IDX(warp) * NC];

#pragma unroll
    for (int d = 8; d <= 16; d += 8) {
        int pf = warp + d;
        if (pf < NPB && lane < 16)
            asm volatile("prefetch.global.L2 [%0];" ::
                "l"((const char*)(nbase + (size_t)IDX(pf) * KO) + lane * 128));
    }

#pragma unroll 1
    for (int nn = warp; nn < NPB; nn += 8) {
        // ---- L2 prefetch 3 rounds ahead (one warp-instr, lanes 0..15) ----
        {
            int pf = nn + 24;
            if (pf < NPB && lane < 16)
                asm volatile("prefetch.global.L2 [%0];" ::
                    "l"((const char*)(nbase + (size_t)IDX(pf) * KO) + lane * 128));
        }

        // ---- register prefetch node nn+8 (likely L2 hit) ----
        const int nnn = (nn + 8 < NPB) ? nn + 8 : nn;
        uint4 un[4];
        {
            const uint4* rp = (const uint4*)(base + (size_t)IDX(nnn) * KO);
#pragma unroll
            for (int q = 0; q < 4; q++) un[q] = rp[q];
        }
        float lgn = 0.f;
        if (ITER == 2) lgn = lbase[IDX(nnn) * NC];

        // ---- compute on current node ----
        const __half2* ph = (const __half2*)u;   // 16 half2 = 32 o-values
        float prob;
        if (ITER == 0) {
            prob = 1.0f / NC;
        } else {
            // delta = dot(p, out[k]) via 4 independent HFMA2 chains
            __half2 dh0 = __float2half2_rn(0.f), dh1 = dh0, dh2 = dh0, dh3 = dh0;
#pragma unroll
            for (int r = 0; r < 16; r += 4) {
                dh0 = __hfma2(ph[r + 0], s_outh[lane][r + 0], dh0);
                dh1 = __hfma2(ph[r + 1], s_outh[lane][r + 1], dh1);
                dh2 = __hfma2(ph[r + 2], s_outh[lane][r + 2], dh2);
                dh3 = __hfma2(ph[r + 3], s_outh[lane][r + 3], dh3);
            }
            float2 f0 = __half22float2(__hadd2(dh0, dh1));
            float2 f1 = __half22float2(__hadd2(dh2, dh3));
            float d = (f0.x + f0.y) + (f1.x + f1.y);

            float logit = d;
            if (ITER == 2) logit += lg;
            if (ITER == 1)
                g_logits[((size_t)b * NN + n0 + nn) * NC + lane] = d;

            // softmax across the 32 lanes (= capsules)
            float mx = logit;
#pragma unroll
            for (int off = 16; off > 0; off >>= 1)
                mx = fmaxf(mx, __shfl_xor_sync(0xffffffffu, mx, off));
            float e = __expf(logit - mx);
            float se = e;
#pragma unroll
            for (int off = 16; off > 0; off >>= 1)
                se += __shfl_xor_sync(0xffffffffu, se, off);
            prob = e / se;
        }

#pragma unroll
        for (int r = 0; r < 16; r++) {
            float2 pf2 = __half22float2(ph[r]);
            acc[2 * r]     = fmaf(prob, pf2.x, acc[2 * r]);
            acc[2 * r + 1] = fmaf(prob, pf2.y, acc[2 * r + 1]);
        }

        // ---- rotate pipeline ----
#pragma unroll
        for (int q = 0; q < 4; q++) u[q] = un[q];
        lg = lgn;
    }
#undef IDX

    // per-warp accumulators -> shared (conflict-free: 33-stride rows)
#pragma unroll
    for (int j = 0; j < OC; j++) atomicAdd(&s_s[lane * 33 + j], acc[j]);
    __syncthreads();

    for (int idx = threadIdx.x; idx < KO; idx += 256)
        atomicAdd(&g_s[b * KO + idx], s_s[(idx >> 5) * 33 + (idx & 31)]);
}

// ---------------- squash: v = (|s|^2/(1+|s|^2)) * s/|s| -------------------
// Grid: (NC, B), 32 threads (lane = o). Also re-zeros g_s so the next pass /
// next graph replay starts clean (keeps kernel_launch deterministic).
template <bool FINAL>
__global__ void k_squash(float* __restrict__ dst) {
    const int k = blockIdx.x, b = blockIdx.y, o = threadIdx.x;
    const int idx = b * KO + k * OC + o;
    float v = g_s[idx];
    g_s[idx] = 0.f;
    float sq = v * v;
#pragma unroll
    for (int off = 16; off > 0; off >>= 1)
        sq += __shfl_xor_sync(0xffffffffu, sq, off);
    float scale = sqrtf(sq) / (1.f + sq);   // = (sq/(1+sq)) / sqrt(sq)
    float out = v * scale;
    if (FINAL) dst[idx] = out;
    else       g_out[idx] = out;
}

// ---------------- launch ----------------------------------------------------
extern "C" void kernel_launch(void* const* d_in, const int* in_sizes, int n_in,
                              void* d_out, int out_size) {
    const float* x = (const float*)d_in[0];          // [B, NN, IC]
    const float* w = (const float*)d_in[1];          // [NN, NC, IC, OC]
    float* out = (float*)d_out;                      // [B, 1, NC, OC]

    k_priors<<<NN, 256>>>(x, w);

    k_iter<0><<<dim3(NCHUNK, B), 256>>>();
    k_squash<false><<<dim3(NC, B), 32>>>(nullptr);

    k_iter<1><<<dim3(NCHUNK, B), 256>>>();
    k_squash<false><<<dim3(NC, B), 32>>>(nullptr);

    k_iter<2><<<dim3(NCHUNK, B), 256>>>();
    k_squash<true><<<dim3(NC, B), 32>>>(out);
}

// round 10
// speedup vs baseline: 1.1686x; 1.1306x over previous
#include <cuda_runtime.h>
#include <cuda_fp16.h>
#include <cstdint>

// Problem dims
#define B   64
#define NN  2048
#define NC  32
#define IC  16
#define OC  32
#define KO  (NC * OC)      // 1024
#define NCHUNK 32          // blocks per batch for k_iter (128-thr blocks)
#define NPB (NN / NCHUNK)  // 64 nodes per block -> 16 per warp (4 warps)

// ---------------- scratch (device globals; no runtime allocation) ----------
__device__ __half g_priors[(size_t)B * NN * KO];   // 268 MB fp16 priors [b][n][k][o]
__device__ float  g_logits[(size_t)B * NN * NC];   // 16 MB  logits  [b][n][k]
__device__ float  g_s[B * KO];                     // s accumulator (zeroed by squash)
__device__ float  g_out[B * KO];                   // current outputs v_i

// ---------------- pass 0: priors = einsum('bni,nkio->bnko'), fp16 store ----
// One block per node n. W[n] (32x16x32 fp32 = 64KB) lives in registers,
// reused across all 64 batches. Packed f32x2 FMA doubles fp32 throughput.
__global__ void __launch_bounds__(256) k_priors(const float* __restrict__ x,
                                                const float* __restrict__ w) {
    const int n  = blockIdx.x;
    const int t  = threadIdx.x;
    const int k  = t >> 3;            // capsule 0..31
    const int og = (t & 7) * 4;       // out-channel group (4 consecutive o)

    // x packed as (v,v) f32x2 per element for broadcast FMA
    __shared__ unsigned long long sx[B][IC];   // 8 KB

    for (int idx = t; idx < B * IC; idx += 256) {
        int b = idx >> 4, i = idx & 15;
        float v = x[((size_t)b * NN + n) * IC + i];
        unsigned long long pv;
        asm("mov.b64 %0, {%1, %2};" : "=l"(pv) : "f"(v), "f"(v));
        sx[b][i] = pv;
    }

    // Load this thread's W slice: W[n][k][0..15][og..og+3] -> 32 packed pairs
    unsigned long long wp[2 * IC];
    const float* wbase = w + (((size_t)n * NC + k) * IC) * OC + og;
#pragma unroll
    for (int i = 0; i < IC; i++) {
        ulonglong2 v = *(const ulonglong2*)(wbase + (size_t)i * OC);
        wp[2 * i]     = v.x;   // (w[og],   w[og+1])
        wp[2 * i + 1] = v.y;   // (w[og+2], w[og+3])
    }
    __syncthreads();

    __half* pout = g_priors + (size_t)n * KO + (size_t)k * OC + og;
#pragma unroll 1
    for (int b = 0; b < B; b++) {
        unsigned long long a0 = 0ull, a1 = 0ull;
#pragma unroll
        for (int i = 0; i < IC; i++) {
            unsigned long long xv = sx[b][i];
            asm("fma.rn.f32x2 %0, %1, %2, %0;" : "+l"(a0) : "l"(xv), "l"(wp[2 * i]));
            asm("fma.rn.f32x2 %0, %1, %2, %0;" : "+l"(a1) : "l"(xv), "l"(wp[2 * i + 1]));
        }
        float f0, f1, f2, f3;
        asm("mov.b64 {%0, %1}, %2;" : "=f"(f0), "=f"(f1) : "l"(a0));
        asm("mov.b64 {%0, %1}, %2;" : "=f"(f2), "=f"(f3) : "l"(a1));
        __half2 h01 = __floats2half2_rn(f0, f1);
        __half2 h23 = __floats2half2_rn(f2, f3);
        uint2 st;
        st.x = *(const unsigned int*)&h01;
        st.y = *(const unsigned int*)&h23;
        *(uint2*)(pout + (size_t)b * NN * KO) = st;
    }
}

// ---------------- routing pass (fused delta + softmax + weighted sum) ------
// Grid: (NCHUNK, B), 128-thread CTAs, 5 CTAs/SM -> 20 warps/SM of latency
// cover (vs 16 before). One warp processes one node at a time: lane = k.
// Depth-1 register prefetch only (measured best; extra LSU instrs regress).
// Softmax WITHOUT max-subtraction: logits bounded (|delta| <= ||p||*||out||,
// ||out|| < 1 from squash) so expf is safe in fp32.
// ITER==0 walks nodes in REVERSE (tail of k_priors' stream still in L2).
template <int ITER>
__global__ void __launch_bounds__(128, 5) k_iter() {
    const int b    = blockIdx.y;
    const int warp = threadIdx.x >> 5;     // 0..3
    const int lane = threadIdx.x & 31;     // capsule index k

    __shared__ float   s_s[NC * 33];       // padded: bank-conflict-free
    __shared__ __half2 s_outh[NC][17];     // out row as half2 pairs, padded

    for (int idx = threadIdx.x; idx < NC * 33; idx += 128) s_s[idx] = 0.f;
    if (ITER > 0) {
        const float2* op = (const float2*)g_out + b * (KO / 2);
        for (int idx = threadIdx.x; idx < KO / 2; idx += 128) {
            int k = idx >> 4, r = idx & 15;
            s_outh[k][r] = __float22half2_rn(op[idx]);
        }
    }
    __syncthreads();

    float acc[OC];
#pragma unroll
    for (int j = 0; j < OC; j++) acc[j] = 0.f;

    const int n0 = blockIdx.x * NPB;
    const __half* base  = g_priors + ((size_t)b * NN + n0) * KO + (size_t)lane * OC;
    const float*  lbase = g_logits + ((size_t)b * NN + n0) * NC + lane;

    // address-only node remap: ITER 0 consumes nodes in reverse order
#define IDX(v) ((ITER == 0) ? (NPB - 1 - (v)) : (v))

    // prologue: register-load first node
    uint4 u[4];
    {
        const uint4* rp = (const uint4*)(base + (size_t)IDX(warp) * KO);
#pragma unroll
        for (int q = 0; q < 4; q++) u[q] = rp[q];
    }
    float lg = 0.f;
    if (ITER == 2) lg = lbase[IDX(warp) * NC];

#pragma unroll 1
    for (int nn = warp; nn < NPB; nn += 4) {
        // ---- register prefetch node nn+4 (depth-1) ----
        const int nnn = (nn + 4 < NPB) ? nn + 4 : nn;
        uint4 un[4];
        {
            const uint4* rp = (const uint4*)(base + (size_t)IDX(nnn) * KO);
#pragma unroll
            for (int q = 0; q < 4; q++) un[q] = rp[q];
        }
        float lgn = 0.f;
        if (ITER == 2) lgn = lbase[IDX(nnn) * NC];

        // ---- compute on current node ----
        const __half2* ph = (const __half2*)u;   // 16 half2 = 32 o-values
        float prob;
        if (ITER == 0) {
            prob = 1.0f / NC;
        } else {
            // delta = dot(p, out[k]) via 4 independent HFMA2 chains
            __half2 dh0 = __float2half2_rn(0.f), dh1 = dh0, dh2 = dh0, dh3 = dh0;
#pragma unroll
            for (int r = 0; r < 16; r += 4) {
                dh0 = __hfma2(ph[r + 0], s_outh[lane][r + 0], dh0);
                dh1 = __hfma2(ph[r + 1], s_outh[lane][r + 1], dh1);
                dh2 = __hfma2(ph[r + 2], s_outh[lane][r + 2], dh2);
                dh3 = __hfma2(ph[r + 3], s_outh[lane][r + 3], dh3);
            }
            float2 f0 = __half22float2(__hadd2(dh0, dh1));
            float2 f1 = __half22float2(__hadd2(dh2, dh3));
            float d = (f0.x + f0.y) + (f1.x + f1.y);

            float logit = d;
            if (ITER == 2) logit += lg;
            if (ITER == 1)
                g_logits[((size_t)b * NN + n0 + nn) * NC + lane] = d;

            // softmax across 32 lanes, no max-subtraction (bounded logits)
            float e = __expf(logit);
            float se = e;
#pragma unroll
            for (int off = 16; off > 0; off >>= 1)
                se += __shfl_xor_sync(0xffffffffu, se, off);
            prob = __fdividef(e, se);
        }

#pragma unroll
        for (int r = 0; r < 16; r++) {
            float2 pf2 = __half22float2(ph[r]);
            acc[2 * r]     = fmaf(prob, pf2.x, acc[2 * r]);
            acc[2 * r + 1] = fmaf(prob, pf2.y, acc[2 * r + 1]);
        }

        // ---- rotate pipeline ----
#pragma unroll
        for (int q = 0; q < 4; q++) u[q] = un[q];
        lg = lgn;
    }
#undef IDX

    // per-warp accumulators -> shared (conflict-free: 33-stride rows)
#pragma unroll
    for (int j = 0; j < OC; j++) atomicAdd(&s_s[lane * 33 + j], acc[j]);
    __syncthreads();

    for (int idx = threadIdx.x; idx < KO; idx += 128)
        atomicAdd(&g_s[b * KO + idx], s_s[(idx >> 5) * 33 + (idx & 31)]);
}

// ---------------- squash: v = (|s|^2/(1+|s|^2)) * s/|s| -------------------
// Grid: (NC, B), 32 threads (lane = o). Also re-zeros g_s so the next pass /
// next graph replay starts clean (keeps kernel_launch deterministic).
template <bool FINAL>
__global__ void k_squash(float* __restrict__ dst) {
    const int k = blockIdx.x, b = blockIdx.y, o = threadIdx.x;
    const int idx = b * KO + k * OC + o;
    float v = g_s[idx];
    g_s[idx] = 0.f;
    float sq = v * v;
#pragma unroll
    for (int off = 16; off > 0; off >>= 1)
        sq += __shfl_xor_sync(0xffffffffu, sq, off);
    float scale = sqrtf(sq) / (1.f + sq);   // = (sq/(1+sq)) / sqrt(sq)
    float out = v * scale;
    if (FINAL) dst[idx] = out;
    else       g_out[idx] = out;
}

// ---------------- launch ----------------------------------------------------
extern "C" void kernel_launch(void* const* d_in, const int* in_sizes, int n_in,
                              void* d_out, int out_size) {
    const float* x = (const float*)d_in[0];          // [B, NN, IC]
    const float* w = (const float*)d_in[1];          // [NN, NC, IC, OC]
    float* out = (float*)d_out;                      // [B, 1, NC, OC]

    k_priors<<<NN, 256>>>(x, w);

    k_iter<0><<<dim3(NCHUNK, B), 128>>>();
    k_squash<false><<<dim3(NC, B), 32>>>(nullptr);

    k_iter<1><<<dim3(NCHUNK, B), 128>>>();
    k_squash<false><<<dim3(NC, B), 32>>>(nullptr);

    k_iter<2><<<dim3(NCHUNK, B), 128>>>();
    k_squash<true><<<dim3(NC, B), 32>>>(out);
}